// round 5
// baseline (speedup 1.0000x reference)
#include <cuda_runtime.h>
#include <cuda_fp16.h>
#include <math.h>

#define NB 4
#define NC 128
#define NH 256
#define NW 256
#define NHW (NH*NW)
#define NBC (NB*NC)      // 512 (b,c) planes
#define CM 16
#define PYR_ELEMS 21844  // 128^2+64^2+32^2+16^2+8^2+4^2+2^2

// scratch (device globals: no allocation allowed)
__device__ float   g_thr[2*NBC];
__device__ __half2 g_M0[(size_t)NBC*NHW];        // (pos,neg) packed: max(init, down0)
__device__ __half2 g_r1[(size_t)NBC*128*128];    // resize(down0 -> 128) both signs
__device__ float2  g_pyr[(size_t)NBC*PYR_ELEMS]; // levels 1..7, (pos,neg)
__device__ __half  g_rad[(size_t)NBC*NHW];       // radiance = Lp - Ln

__device__ __constant__ float c_scf[7] = {
    (float)(127.0/255.0), (float)(63.0/255.0), (float)(31.0/255.0),
    (float)(15.0/255.0),  (float)(7.0/255.0),  (float)(3.0/255.0),
    (float)(1.0/255.0)
};
__device__ __constant__ int c_soff[7] = {0, 0, 4096, 5120, 5376, 5440, 5456}; // smem offsets (k>=1)

__device__ __forceinline__ float sigmoid_f(float t) { return 1.0f / (1.0f + __expf(-t)); }

// ------------------------------------------------------------------ K0: stats
__global__ void __launch_bounds__(256) k_stats(const float* __restrict__ x) {
    int plane = blockIdx.x;
    const float4* p = (const float4*)(x + (size_t)plane * NHW);
    float sp = 0.f, s2p = 0.f, sn = 0.f, s2n = 0.f;
    for (int i = threadIdx.x; i < NHW/4; i += 256) {
        float4 v = __ldg(p + i);
        float a;
        a = fmaxf(v.x,0.f); sp += a; s2p = fmaf(a,a,s2p); a = fmaxf(-v.x,0.f); sn += a; s2n = fmaf(a,a,s2n);
        a = fmaxf(v.y,0.f); sp += a; s2p = fmaf(a,a,s2p); a = fmaxf(-v.y,0.f); sn += a; s2n = fmaf(a,a,s2n);
        a = fmaxf(v.z,0.f); sp += a; s2p = fmaf(a,a,s2p); a = fmaxf(-v.z,0.f); sn += a; s2n = fmaf(a,a,s2n);
        a = fmaxf(v.w,0.f); sp += a; s2p = fmaf(a,a,s2p); a = fmaxf(-v.w,0.f); sn += a; s2n = fmaf(a,a,s2n);
    }
    __shared__ float red[8][4];
    #pragma unroll
    for (int o = 16; o; o >>= 1) {
        sp  += __shfl_down_sync(0xffffffffu, sp,  o);
        s2p += __shfl_down_sync(0xffffffffu, s2p, o);
        sn  += __shfl_down_sync(0xffffffffu, sn,  o);
        s2n += __shfl_down_sync(0xffffffffu, s2n, o);
    }
    int lane = threadIdx.x & 31, w = threadIdx.x >> 5;
    if (lane == 0) { red[w][0] = sp; red[w][1] = s2p; red[w][2] = sn; red[w][3] = s2n; }
    __syncthreads();
    if (threadIdx.x == 0) {
        float SP=0,S2P=0,SN=0,S2N=0;
        for (int i = 0; i < 8; i++) { SP+=red[i][0]; S2P+=red[i][1]; SN+=red[i][2]; S2N+=red[i][3]; }
        const float N = (float)NHW;
        float vp = fmaxf((S2P - SP*SP/N) / (N - 1.f), 0.f);
        g_thr[plane]       = SP/N + 2.f * sqrtf(vp);
        float vn = fmaxf((S2N - SN*SN/N) / (N - 1.f), 0.f);
        g_thr[NBC + plane] = SN/N + 2.f * sqrtf(vn);
    }
}

// -------------------------------------------------- K1: init + M0 + r1 samples
__global__ void __launch_bounds__(256) k_init(const float* __restrict__ x) {
    __shared__ float ip[35][36], inn[35][36];   // init with halo rows ty0-1 .. ty0+33
    __shared__ float dp[33][36], dn[33][36];    // down0 rows ty0 .. ty0+32
    const int bc  = blockIdx.z;
    const int tx0 = blockIdx.x * 32, ty0 = blockIdx.y * 32;
    const float thp = g_thr[bc], thn = g_thr[NBC + bc];
    const float* xp = x + (size_t)bc * NHW;
    const int tid = threadIdx.x;

    for (int idx = tid; idx < 35*35; idx += 256) {
        int r = idx / 35, c = idx % 35;
        int gy = ty0 - 1 + r; gy = min(max(gy, 0), NH-1);
        int gx = tx0 - 1 + c; gx = min(max(gx, 0), NW-1);
        float v  = __ldg(xp + gy*NW + gx);
        float vp = fmaxf(v, 0.f);
        float vn = fmaxf(-v, 0.f);
        ip[r][c]  = vp * (sigmoid_f(100.f*(vp - thp)) + 1e-6f);
        inn[r][c] = vn * (sigmoid_f(100.f*(vn - thn)) + 1e-6f);
    }
    __syncthreads();
    for (int idx = tid; idx < 33*33; idx += 256) {
        int r = idx / 33, c = idx % 33;
        float mp = 0.f, mn = 0.f;
        #pragma unroll
        for (int dr = 0; dr < 3; dr++)
        #pragma unroll
        for (int dc = 0; dc < 3; dc++) {
            mp = fmaxf(mp, ip[r+dr][c+dc]);
            mn = fmaxf(mn, inn[r+dr][c+dc]);
        }
        dp[r][c] = 0.99f * mp;
        dn[r][c] = 0.99f * mn;
    }
    __syncthreads();
    for (int idx = tid; idx < 32*32; idx += 256) {
        int r = idx >> 5, c = idx & 31;
        float m0p = fmaxf(ip[r+1][c+1], dp[r][c]);
        float m0n = fmaxf(inn[r+1][c+1], dn[r][c]);
        g_M0[(size_t)bc*NHW + (size_t)(ty0+r)*NW + (tx0+c)] = __floats2half2_rn(m0p, m0n);
    }
    // r1 = resize(down0 -> 128, align_corners). Tile owns (i,j) iff floor(i*A1)
    // in [ty0,ty0+31] and floor(j*A1) in [tx0,tx0+31] (same fp expr as below).
    const float A1 = 255.0f / 127.0f;
    int i_lo = max(0, (int)((float)ty0 / A1) - 1);
    while (i_lo < 128 && (int)((float)i_lo * A1) < ty0) i_lo++;
    int i_hi = min(127, (int)((float)(ty0+32) / A1) + 1);
    while (i_hi >= i_lo && (int)((float)i_hi * A1) > ty0+31) i_hi--;
    int j_lo = max(0, (int)((float)tx0 / A1) - 1);
    while (j_lo < 128 && (int)((float)j_lo * A1) < tx0) j_lo++;
    int j_hi = min(127, (int)((float)(tx0+32) / A1) + 1);
    while (j_hi >= j_lo && (int)((float)j_hi * A1) > tx0+31) j_hi--;
    int ni = i_hi - i_lo + 1; if (ni < 0) ni = 0;
    int nj = j_hi - j_lo + 1; if (nj < 0) nj = 0;
    for (int idx = tid; idx < ni*nj; idx += 256) {
        int i = i_lo + idx / nj;
        int j = j_lo + idx % nj;
        float fy = (float)i * A1; int i0 = (int)fy; float wy = fy - (float)i0;
        int i1 = min(i0 + 1, NH-1);
        float fx = (float)j * A1; int j0 = (int)fx; float wx = fx - (float)j0;
        int j1 = min(j0 + 1, NW-1);
        int li0 = i0 - ty0, li1 = i1 - ty0, lj0 = j0 - tx0, lj1 = j1 - tx0;
        float vp = (1.f-wy)*((1.f-wx)*dp[li0][lj0] + wx*dp[li0][lj1])
                 +      wy *((1.f-wx)*dp[li1][lj0] + wx*dp[li1][lj1]);
        float vn = (1.f-wy)*((1.f-wx)*dn[li0][lj0] + wx*dn[li0][lj1])
                 +      wy *((1.f-wx)*dn[li1][lj0] + wx*dn[li1][lj1]);
        g_r1[(size_t)bc*16384 + i*128 + j] = __floats2half2_rn(vp, vn);
    }
}

// ----------------------------------------------- K2: pyramid levels 1..7 (fp32)
#define SMEM_PYR (16384*4 + 4096*8)   // S: 16384 half2, R: 4096 float2
__global__ void __launch_bounds__(256) k_pyr() {
    extern __shared__ unsigned char smraw[];
    __half2* S = (__half2*)smraw;                 // r1 staging
    float2*  R = (float2*)(smraw + 16384*4);      // resize buffer (<= 64x64)
    const int bc = blockIdx.x, tid = threadIdx.x;
    const __half2* r1p = g_r1 + (size_t)bc * 16384;
    float2* pyr = g_pyr + (size_t)bc * PYR_ELEMS;

    for (int i = tid; i < 16384; i += 256) S[i] = __ldg(r1p + i);
    __syncthreads();
    // level 1 (size 128): down1 = gamma^2 * maxpool3(r1)
    for (int idx = tid; idx < 16384; idx += 256) {
        int i = idx >> 7, j = idx & 127;
        float mp = 0.f, mn = 0.f;
        #pragma unroll
        for (int dr = -1; dr <= 1; dr++) {
            int ii = min(max(i+dr,0),127) << 7;
            #pragma unroll
            for (int dc = -1; dc <= 1; dc++) {
                int jj = min(max(j+dc,0),127);
                float2 v = __half22float2(S[ii + jj]);
                mp = fmaxf(mp, v.x); mn = fmaxf(mn, v.y);
            }
        }
        pyr[idx] = make_float2(0.9801f*mp, 0.9801f*mn);
    }
    __syncthreads();   // block-visible gmem writes
    int off_in = 0, off_out = 16384, sin = 128;
    double gd = 0.9801;
    for (int k = 2; k <= 7; k++) {
        int sout = sin >> 1;
        float ak = (float)((double)(sin-1) / (double)(sout-1));
        const float2* Lv = pyr + off_in;
        for (int idx = tid; idx < sout*sout; idx += 256) {
            int i = idx / sout, j = idx % sout;
            float fy = (float)i * ak; int i0 = (int)fy; float wy = fy - (float)i0; int i1 = min(i0+1, sin-1);
            float fx = (float)j * ak; int j0 = (int)fx; float wx = fx - (float)j0; int j1 = min(j0+1, sin-1);
            float2 a = Lv[i0*sin+j0], b = Lv[i0*sin+j1], c = Lv[i1*sin+j0], d = Lv[i1*sin+j1];
            R[idx] = make_float2(
                (1.f-wy)*((1.f-wx)*a.x + wx*b.x) + wy*((1.f-wx)*c.x + wx*d.x),
                (1.f-wy)*((1.f-wx)*a.y + wx*b.y) + wy*((1.f-wx)*c.y + wx*d.y));
        }
        __syncthreads();
        gd *= gd;                         // gamma^(2^k)
        float gk = (float)gd;
        for (int idx = tid; idx < sout*sout; idx += 256) {
            int i = idx / sout, j = idx % sout;
            float mp = 0.f, mn = 0.f;
            #pragma unroll
            for (int dr = -1; dr <= 1; dr++) {
                int ii = min(max(i+dr,0),sout-1) * sout;
                #pragma unroll
                for (int dc = -1; dc <= 1; dc++) {
                    int jj = min(max(j+dc,0),sout-1);
                    float2 v = R[ii + jj];
                    mp = fmaxf(mp, v.x); mn = fmaxf(mn, v.y);
                }
            }
            pyr[off_out + idx] = make_float2(gk*mp, gk*mn);
        }
        __syncthreads();
        off_in = off_out; off_out += sout*sout; sin = sout;
    }
}

// --------------------------------- K3: per-plane radiance via rowbuf bilinears
__global__ void __launch_bounds__(256) k_field() {
    __shared__ float2 spyr[5460];   // levels 64^2..2^2
    __shared__ float2 rb[254];      // H-lerped rows of all 7 levels
    const int bc = blockIdx.x;
    const int tid = threadIdx.x;
    const float2* pyr = g_pyr + (size_t)bc * PYR_ELEMS;
    for (int i = tid; i < 5460; i += 256) spyr[i] = __ldg(&pyr[16384 + i]);

    // per-thread (column) x-interp constants per level
    int j0a[7], j1a[7]; float wxa[7];
    #pragma unroll
    for (int k = 0; k < 7; k++) {
        int s = 128 >> k;
        float fx = (float)tid * c_scf[k];
        int j0 = (int)fx; float wx = fx - (float)j0; int j1 = min(j0+1, s-1);
        j0a[k] = j0; j1a[k] = j1; wxa[k] = wx;
    }
    __syncthreads();

    const int rboff[7] = {0, 128, 192, 224, 240, 248, 252};
    const __half2* M0p = g_M0 + (size_t)bc * NHW;
    __half* radp = g_rad + (size_t)bc * NHW;

    for (int y = 0; y < NH; y++) {
        if (tid < 254) {
            int k, j;
            if      (tid < 128) { k = 0; j = tid;       }
            else if (tid < 192) { k = 1; j = tid - 128; }
            else if (tid < 224) { k = 2; j = tid - 192; }
            else if (tid < 240) { k = 3; j = tid - 224; }
            else if (tid < 248) { k = 4; j = tid - 240; }
            else if (tid < 252) { k = 5; j = tid - 248; }
            else                { k = 6; j = tid - 252; }
            int s = 128 >> k;
            float fy = (float)y * c_scf[k];
            int i0 = (int)fy; float wy = fy - (float)i0; int i1 = min(i0+1, s-1);
            float2 a, b;
            if (k == 0) { a = __ldg(&pyr[i0*128 + j]); b = __ldg(&pyr[i1*128 + j]); }
            else { int so = c_soff[k]; a = spyr[so + i0*s + j]; b = spyr[so + i1*s + j]; }
            rb[tid] = make_float2((1.f-wy)*a.x + wy*b.x, (1.f-wy)*a.y + wy*b.y);
        }
        __syncthreads();
        float Up = 0.f, Un = 0.f;   // all fields >= 0
        #pragma unroll
        for (int k = 0; k < 7; k++) {
            float2 a = rb[rboff[k] + j0a[k]];
            float2 b = rb[rboff[k] + j1a[k]];
            float w = wxa[k], om = 1.f - w;
            Up = fmaxf(Up, om*a.x + w*b.x);
            Un = fmaxf(Un, om*a.y + w*b.y);
        }
        float2 m0 = __half22float2(__ldg(M0p + y*NW + tid));
        float rad = fmaxf(m0.x, Up) - fmaxf(m0.y, Un);
        radp[y*NW + tid] = __float2half_rn(rad);
        __syncthreads();
    }
}

// ------------------------------------------- K4: 1x1-conv MLP + modulate (2 px/thread)
__global__ void __launch_bounds__(256) k_mlp(
    const float* __restrict__ x,
    const float* __restrict__ w1, const float* __restrict__ b1,
    const float* __restrict__ w2, const float* __restrict__ b2,
    float* __restrict__ out)
{
    __shared__ float sw1[CM*NC], sw2[NC*CM], sb1[CM], sb2[NC];
    const int tid = threadIdx.x;
    for (int i = tid; i < CM*NC; i += 256) { sw1[i] = w1[i]; sw2[i] = w2[i]; }
    if (tid < CM) sb1[tid] = b1[tid];
    if (tid < NC) sb2[tid] = b2[tid];
    __syncthreads();

    int g  = blockIdx.x * 256 + tid;      // pixel-pair index
    int b  = g >> 15;                     // 32768 pairs per batch
    int hw = (g & 32767) << 1;
    const __half2* rp = (const __half2*)(g_rad + ((size_t)(b*NC) << 16) + hw);
    const float2*  xp = (const float2*) (x     + ((size_t)(b*NC) << 16) + hw);
    float2*        op = (float2*)       (out   + ((size_t)(b*NC) << 16) + hw);

    float h0[CM], h1[CM];
    #pragma unroll
    for (int o = 0; o < CM; o++) { h0[o] = sb1[o]; h1[o] = sb1[o]; }
    for (int c = 0; c < NC; c++) {
        float2 r = __half22float2(__ldg(rp + ((size_t)c << 15)));
        #pragma unroll
        for (int o = 0; o < CM; o++) {
            float w = sw1[o*NC + c];
            h0[o] = fmaf(w, r.x, h0[o]);
            h1[o] = fmaf(w, r.y, h1[o]);
        }
    }
    #pragma unroll
    for (int o = 0; o < CM; o++) { h0[o] = fmaxf(h0[o], 0.f); h1[o] = fmaxf(h1[o], 0.f); }
    for (int c = 0; c < NC; c++) {
        float a0 = sb2[c], a1 = sb2[c];
        #pragma unroll
        for (int o = 0; o < CM; o++) {
            float w = sw2[c*CM + o];
            a0 = fmaf(w, h0[o], a0);
            a1 = fmaf(w, h1[o], a1);
        }
        float2 xv = __ldg(xp + ((size_t)c << 15));
        float2 ov;
        ov.x = xv.x * sigmoid_f(a0);
        ov.y = xv.y * sigmoid_f(a1);
        op[(size_t)c << 15] = ov;
    }
}

extern "C" void kernel_launch(void* const* d_in, const int* in_sizes, int n_in,
                              void* d_out, int out_size) {
    const float* x  = (const float*)d_in[0];
    const float* w1 = (const float*)d_in[1];
    const float* b1 = (const float*)d_in[2];
    const float* w2 = (const float*)d_in[3];
    const float* b2 = (const float*)d_in[4];
    float* out = (float*)d_out;

    cudaFuncSetAttribute(k_pyr, cudaFuncAttributeMaxDynamicSharedMemorySize, SMEM_PYR);

    k_stats<<<NBC, 256>>>(x);
    k_init<<<dim3(8, 8, NBC), 256>>>(x);
    k_pyr<<<NBC, 256, SMEM_PYR>>>();
    k_field<<<NBC, 256>>>();
    k_mlp<<<(NB*NHW)/512, 256>>>(x, w1, b1, w2, b2, out);
}

// round 6
// speedup vs baseline: 1.5504x; 1.5504x over previous
#include <cuda_runtime.h>
#include <cuda_fp16.h>
#include <math.h>

#define NB 4
#define NC 128
#define NH 256
#define NW 256
#define NHW (NH*NW)
#define NBC (NB*NC)      // 512 (b,c) planes
#define CM 16
#define PYR_ELEMS 21844  // 128^2+64^2+32^2+16^2+8^2+4^2+2^2

// scratch (device globals: no allocation allowed)
__device__ float   g_thr[2*NBC];
__device__ __half2 g_M0[(size_t)NBC*NHW];        // (pos,neg) packed: max(init, down0)
__device__ __half2 g_r1[(size_t)NBC*128*128];    // resize(down0 -> 128) both signs
__device__ float2  g_pyr[(size_t)NBC*PYR_ELEMS]; // levels 1..7, (pos,neg)
__device__ __half  g_rad[(size_t)NBC*NHW];       // radiance = Lp - Ln

__device__ __constant__ float c_scf[7] = {
    (float)(127.0/255.0), (float)(63.0/255.0), (float)(31.0/255.0),
    (float)(15.0/255.0),  (float)(7.0/255.0),  (float)(3.0/255.0),
    (float)(1.0/255.0)
};
__device__ __constant__ int c_soff[7] = {0, 0, 4096, 5120, 5376, 5440, 5456}; // spyr offsets (k>=1)

__device__ __forceinline__ float sigmoid_f(float t) { return 1.0f / (1.0f + __expf(-t)); }

// ------------------------------------------------------------------ K0: stats
__global__ void __launch_bounds__(256) k_stats(const float* __restrict__ x) {
    int plane = blockIdx.x;
    const float4* p = (const float4*)(x + (size_t)plane * NHW);
    float sp = 0.f, s2p = 0.f, sn = 0.f, s2n = 0.f;
    for (int i = threadIdx.x; i < NHW/4; i += 256) {
        float4 v = __ldg(p + i);
        float a;
        a = fmaxf(v.x,0.f); sp += a; s2p = fmaf(a,a,s2p); a = fmaxf(-v.x,0.f); sn += a; s2n = fmaf(a,a,s2n);
        a = fmaxf(v.y,0.f); sp += a; s2p = fmaf(a,a,s2p); a = fmaxf(-v.y,0.f); sn += a; s2n = fmaf(a,a,s2n);
        a = fmaxf(v.z,0.f); sp += a; s2p = fmaf(a,a,s2p); a = fmaxf(-v.z,0.f); sn += a; s2n = fmaf(a,a,s2n);
        a = fmaxf(v.w,0.f); sp += a; s2p = fmaf(a,a,s2p); a = fmaxf(-v.w,0.f); sn += a; s2n = fmaf(a,a,s2n);
    }
    __shared__ float red[8][4];
    #pragma unroll
    for (int o = 16; o; o >>= 1) {
        sp  += __shfl_down_sync(0xffffffffu, sp,  o);
        s2p += __shfl_down_sync(0xffffffffu, s2p, o);
        sn  += __shfl_down_sync(0xffffffffu, sn,  o);
        s2n += __shfl_down_sync(0xffffffffu, s2n, o);
    }
    int lane = threadIdx.x & 31, w = threadIdx.x >> 5;
    if (lane == 0) { red[w][0] = sp; red[w][1] = s2p; red[w][2] = sn; red[w][3] = s2n; }
    __syncthreads();
    if (threadIdx.x == 0) {
        float SP=0,S2P=0,SN=0,S2N=0;
        for (int i = 0; i < 8; i++) { SP+=red[i][0]; S2P+=red[i][1]; SN+=red[i][2]; S2N+=red[i][3]; }
        const float N = (float)NHW;
        float vp = fmaxf((S2P - SP*SP/N) / (N - 1.f), 0.f);
        g_thr[plane]       = SP/N + 2.f * sqrtf(vp);
        float vn = fmaxf((S2N - SN*SN/N) / (N - 1.f), 0.f);
        g_thr[NBC + plane] = SN/N + 2.f * sqrtf(vn);
    }
}

// -------------------------------------------------- K1: init + M0 + r1 samples
__global__ void __launch_bounds__(256) k_init(const float* __restrict__ x) {
    __shared__ float ip[35][36], inn[35][36];   // init with halo rows ty0-1 .. ty0+33
    __shared__ float dp[33][36], dn[33][36];    // down0 rows ty0 .. ty0+32
    const int bc  = blockIdx.z;
    const int tx0 = blockIdx.x * 32, ty0 = blockIdx.y * 32;
    const float thp = g_thr[bc], thn = g_thr[NBC + bc];
    const float* xp = x + (size_t)bc * NHW;
    const int tid = threadIdx.x;

    for (int idx = tid; idx < 35*35; idx += 256) {
        int r = idx / 35, c = idx % 35;
        int gy = ty0 - 1 + r; gy = min(max(gy, 0), NH-1);
        int gx = tx0 - 1 + c; gx = min(max(gx, 0), NW-1);
        float v  = __ldg(xp + gy*NW + gx);
        float vp = fmaxf(v, 0.f);
        float vn = fmaxf(-v, 0.f);
        ip[r][c]  = vp * (sigmoid_f(100.f*(vp - thp)) + 1e-6f);
        inn[r][c] = vn * (sigmoid_f(100.f*(vn - thn)) + 1e-6f);
    }
    __syncthreads();
    for (int idx = tid; idx < 33*33; idx += 256) {
        int r = idx / 33, c = idx % 33;
        float mp = 0.f, mn = 0.f;
        #pragma unroll
        for (int dr = 0; dr < 3; dr++)
        #pragma unroll
        for (int dc = 0; dc < 3; dc++) {
            mp = fmaxf(mp, ip[r+dr][c+dc]);
            mn = fmaxf(mn, inn[r+dr][c+dc]);
        }
        dp[r][c] = 0.99f * mp;
        dn[r][c] = 0.99f * mn;
    }
    __syncthreads();
    for (int idx = tid; idx < 32*32; idx += 256) {
        int r = idx >> 5, c = idx & 31;
        float m0p = fmaxf(ip[r+1][c+1], dp[r][c]);
        float m0n = fmaxf(inn[r+1][c+1], dn[r][c]);
        g_M0[(size_t)bc*NHW + (size_t)(ty0+r)*NW + (tx0+c)] = __floats2half2_rn(m0p, m0n);
    }
    // r1 = resize(down0 -> 128, align_corners). Tile owns (i,j) iff floor(i*A1)
    // in [ty0,ty0+31] and floor(j*A1) in [tx0,tx0+31] (same fp expr as below).
    const float A1 = 255.0f / 127.0f;
    int i_lo = max(0, (int)((float)ty0 / A1) - 1);
    while (i_lo < 128 && (int)((float)i_lo * A1) < ty0) i_lo++;
    int i_hi = min(127, (int)((float)(ty0+32) / A1) + 1);
    while (i_hi >= i_lo && (int)((float)i_hi * A1) > ty0+31) i_hi--;
    int j_lo = max(0, (int)((float)tx0 / A1) - 1);
    while (j_lo < 128 && (int)((float)j_lo * A1) < tx0) j_lo++;
    int j_hi = min(127, (int)((float)(tx0+32) / A1) + 1);
    while (j_hi >= j_lo && (int)((float)j_hi * A1) > tx0+31) j_hi--;
    int ni = i_hi - i_lo + 1; if (ni < 0) ni = 0;
    int nj = j_hi - j_lo + 1; if (nj < 0) nj = 0;
    for (int idx = tid; idx < ni*nj; idx += 256) {
        int i = i_lo + idx / nj;
        int j = j_lo + idx % nj;
        float fy = (float)i * A1; int i0 = (int)fy; float wy = fy - (float)i0;
        int i1 = min(i0 + 1, NH-1);
        float fx = (float)j * A1; int j0 = (int)fx; float wx = fx - (float)j0;
        int j1 = min(j0 + 1, NW-1);
        int li0 = i0 - ty0, li1 = i1 - ty0, lj0 = j0 - tx0, lj1 = j1 - tx0;
        float vp = (1.f-wy)*((1.f-wx)*dp[li0][lj0] + wx*dp[li0][lj1])
                 +      wy *((1.f-wx)*dp[li1][lj0] + wx*dp[li1][lj1]);
        float vn = (1.f-wy)*((1.f-wx)*dn[li0][lj0] + wx*dn[li0][lj1])
                 +      wy *((1.f-wx)*dn[li1][lj0] + wx*dn[li1][lj1]);
        g_r1[(size_t)bc*16384 + i*128 + j] = __floats2half2_rn(vp, vn);
    }
}

// ----------------------------------------------- K2: pyramid levels 1..7 (fp32)
#define SMEM_PYR (16384*4 + 4096*8)   // S: 16384 half2, R: 4096 float2
__global__ void __launch_bounds__(256) k_pyr() {
    extern __shared__ unsigned char smraw[];
    __half2* S = (__half2*)smraw;                 // r1 staging
    float2*  R = (float2*)(smraw + 16384*4);      // resize buffer (<= 64x64)
    const int bc = blockIdx.x, tid = threadIdx.x;
    const __half2* r1p = g_r1 + (size_t)bc * 16384;
    float2* pyr = g_pyr + (size_t)bc * PYR_ELEMS;

    for (int i = tid; i < 16384; i += 256) S[i] = __ldg(r1p + i);
    __syncthreads();
    // level 1 (size 128): down1 = gamma^2 * maxpool3(r1)
    for (int idx = tid; idx < 16384; idx += 256) {
        int i = idx >> 7, j = idx & 127;
        float mp = 0.f, mn = 0.f;
        #pragma unroll
        for (int dr = -1; dr <= 1; dr++) {
            int ii = min(max(i+dr,0),127) << 7;
            #pragma unroll
            for (int dc = -1; dc <= 1; dc++) {
                int jj = min(max(j+dc,0),127);
                float2 v = __half22float2(S[ii + jj]);
                mp = fmaxf(mp, v.x); mn = fmaxf(mn, v.y);
            }
        }
        pyr[idx] = make_float2(0.9801f*mp, 0.9801f*mn);
    }
    __syncthreads();   // block-visible gmem writes
    int off_in = 0, off_out = 16384, sin = 128;
    double gd = 0.9801;
    for (int k = 2; k <= 7; k++) {
        int sout = sin >> 1;
        float ak = (float)((double)(sin-1) / (double)(sout-1));
        const float2* Lv = pyr + off_in;
        for (int idx = tid; idx < sout*sout; idx += 256) {
            int i = idx / sout, j = idx % sout;
            float fy = (float)i * ak; int i0 = (int)fy; float wy = fy - (float)i0; int i1 = min(i0+1, sin-1);
            float fx = (float)j * ak; int j0 = (int)fx; float wx = fx - (float)j0; int j1 = min(j0+1, sin-1);
            float2 a = Lv[i0*sin+j0], b = Lv[i0*sin+j1], c = Lv[i1*sin+j0], d = Lv[i1*sin+j1];
            R[idx] = make_float2(
                (1.f-wy)*((1.f-wx)*a.x + wx*b.x) + wy*((1.f-wx)*c.x + wx*d.x),
                (1.f-wy)*((1.f-wx)*a.y + wx*b.y) + wy*((1.f-wx)*c.y + wx*d.y));
        }
        __syncthreads();
        gd *= gd;                         // gamma^(2^k)
        float gk = (float)gd;
        for (int idx = tid; idx < sout*sout; idx += 256) {
            int i = idx / sout, j = idx % sout;
            float mp = 0.f, mn = 0.f;
            #pragma unroll
            for (int dr = -1; dr <= 1; dr++) {
                int ii = min(max(i+dr,0),sout-1) * sout;
                #pragma unroll
                for (int dc = -1; dc <= 1; dc++) {
                    int jj = min(max(j+dc,0),sout-1);
                    float2 v = R[ii + jj];
                    mp = fmaxf(mp, v.x); mn = fmaxf(mn, v.y);
                }
            }
            pyr[off_out + idx] = make_float2(gk*mp, gk*mn);
        }
        __syncthreads();
        off_in = off_out; off_out += sout*sout; sin = sout;
    }
}

// --------------------- K3: radiance. 4 rows/iter, double-buffered rowbuf, 1 bar/iter
__global__ void __launch_bounds__(256) k_field() {
    __shared__ __half2 spyr[5460];       // levels 2..7 (64^2..2^2), half2
    __shared__ float2  rb[2][4][256];    // y-lerped rows of all 7 levels
    const int bc  = blockIdx.x;
    const int tid = threadIdx.x;
    const float2* pyr = g_pyr + (size_t)bc * PYR_ELEMS;
    for (int i = tid; i < 5460; i += 256) {
        float2 v = __ldg(&pyr[16384 + i]);
        spyr[i] = __floats2half2_rn(v.x, v.y);
    }

    // consume constants: absolute rb offsets per level for this column
    const int rboff[7] = {0, 128, 192, 224, 240, 248, 252};
    int j0a[7], j1a[7]; float wxa[7], oma[7];
    #pragma unroll
    for (int k = 0; k < 7; k++) {
        int s = 128 >> k;
        float fx = (float)tid * c_scf[k];
        int j0 = (int)fx; float wx = fx - (float)j0; int j1 = min(j0+1, s-1);
        j0a[k] = rboff[k] + j0; j1a[k] = rboff[k] + j1;
        wxa[k] = wx; oma[k] = 1.f - wx;
    }

    // build constants: thread tid builds rowbuf position tid = (level kb, index jb)
    int kb, jb;
    if      (tid < 128) { kb = 0; jb = tid;       }
    else if (tid < 192) { kb = 1; jb = tid - 128; }
    else if (tid < 224) { kb = 2; jb = tid - 192; }
    else if (tid < 240) { kb = 3; jb = tid - 224; }
    else if (tid < 248) { kb = 4; jb = tid - 240; }
    else if (tid < 252) { kb = 5; jb = tid - 248; }
    else                { kb = 6; jb = tid - 252; }
    const bool doB = (tid < 254);
    const int   sb  = 128 >> kb;
    const float scb = c_scf[kb];
    const int   sob = c_soff[kb];
    __syncthreads();   // spyr visible

    // build one y-lerped value for output row y at this thread's (kb, jb)
    auto buildv = [&](int y) -> float2 {
        float fy = (float)y * scb;
        int i0 = (int)fy; float wy = fy - (float)i0; int i1 = min(i0+1, sb-1);
        float2 a, b;
        if (kb == 0) { a = __ldg(&pyr[i0*128 + jb]); b = __ldg(&pyr[i1*128 + jb]); }
        else {
            a = __half22float2(spyr[sob + i0*sb + jb]);
            b = __half22float2(spyr[sob + i1*sb + jb]);
        }
        return make_float2((1.f-wy)*a.x + wy*b.x, (1.f-wy)*a.y + wy*b.y);
    };

    // prologue: rows 0..3 into buffer 0
    if (doB) {
        #pragma unroll
        for (int r = 0; r < 4; r++) rb[0][r][tid] = buildv(r);
    }
    __syncthreads();

    const __half2* M0p = g_M0 + (size_t)bc * NHW + tid;
    __half* radp = g_rad + (size_t)bc * NHW + tid;

    int buf = 0;
    for (int y0 = 0; y0 < NH; y0 += 4) {
        // prefetch next block's build values (loads overlap consume below)
        float2 nb0, nb1, nb2, nb3;
        const bool more = (y0 + 4 < NH);
        if (more && doB) {
            nb0 = buildv(y0+4); nb1 = buildv(y0+5);
            nb2 = buildv(y0+6); nb3 = buildv(y0+7);
        }
        // consume 4 rows at column tid
        #pragma unroll
        for (int r = 0; r < 4; r++) {
            float Up = 0.f, Un = 0.f;   // all fields >= 0
            #pragma unroll
            for (int k = 0; k < 7; k++) {
                float2 a = rb[buf][r][j0a[k]];
                float2 b = rb[buf][r][j1a[k]];
                Up = fmaxf(Up, oma[k]*a.x + wxa[k]*b.x);
                Un = fmaxf(Un, oma[k]*a.y + wxa[k]*b.y);
            }
            float2 m0 = __half22float2(__ldg(M0p + (y0+r)*NW));
            radp[(y0+r)*NW] = __float2half_rn(fmaxf(m0.x, Up) - fmaxf(m0.y, Un));
        }
        if (more && doB) {
            rb[buf^1][0][tid] = nb0; rb[buf^1][1][tid] = nb1;
            rb[buf^1][2][tid] = nb2; rb[buf^1][3][tid] = nb3;
        }
        __syncthreads();
        buf ^= 1;
    }
}

// --------------------------- K4: 1x1-conv MLP + modulate (4 px/thread, vectorized)
__global__ void __launch_bounds__(256) k_mlp(
    const float* __restrict__ x,
    const float* __restrict__ w1, const float* __restrict__ b1,
    const float* __restrict__ w2, const float* __restrict__ b2,
    float* __restrict__ out)
{
    __shared__ float sw1[CM*NC], sw2[NC*CM], sb1[CM], sb2[NC];
    const int tid = threadIdx.x;
    for (int i = tid; i < CM*NC; i += 256) { sw1[i] = w1[i]; sw2[i] = w2[i]; }
    if (tid < CM) sb1[tid] = b1[tid];
    if (tid < NC) sb2[tid] = b2[tid];
    __syncthreads();

    int g  = blockIdx.x * 256 + tid;      // pixel-quad index (65536 total)
    int b  = g >> 14;                     // 16384 quads per batch
    int hw = (g & 16383) << 2;
    size_t base = ((size_t)(b*NC) << 16) + hw;
    const uint2*  rq = (const uint2*) (g_rad + base);
    const float4* xq = (const float4*)(x     + base);
    float4*       oq = (float4*)      (out   + base);

    float h0[CM], h1[CM], h2[CM], h3[CM];
    #pragma unroll
    for (int o = 0; o < CM; o++) { h0[o]=sb1[o]; h1[o]=sb1[o]; h2[o]=sb1[o]; h3[o]=sb1[o]; }
    for (int c = 0; c < NC; c++) {
        uint2 rv = __ldg(rq + ((size_t)c << 14));
        float2 r01 = __half22float2(*(const __half2*)&rv.x);
        float2 r23 = __half22float2(*(const __half2*)&rv.y);
        #pragma unroll
        for (int o = 0; o < CM; o++) {
            float w = sw1[o*NC + c];
            h0[o] = fmaf(w, r01.x, h0[o]);
            h1[o] = fmaf(w, r01.y, h1[o]);
            h2[o] = fmaf(w, r23.x, h2[o]);
            h3[o] = fmaf(w, r23.y, h3[o]);
        }
    }
    #pragma unroll
    for (int o = 0; o < CM; o++) {
        h0[o] = fmaxf(h0[o], 0.f); h1[o] = fmaxf(h1[o], 0.f);
        h2[o] = fmaxf(h2[o], 0.f); h3[o] = fmaxf(h3[o], 0.f);
    }
    for (int c = 0; c < NC; c++) {
        float a0 = sb2[c], a1 = sb2[c], a2 = sb2[c], a3 = sb2[c];
        #pragma unroll
        for (int o = 0; o < CM; o++) {
            float w = sw2[c*CM + o];
            a0 = fmaf(w, h0[o], a0);
            a1 = fmaf(w, h1[o], a1);
            a2 = fmaf(w, h2[o], a2);
            a3 = fmaf(w, h3[o], a3);
        }
        float4 xv = __ldg(xq + ((size_t)c << 14));
        float4 ov;
        ov.x = xv.x * sigmoid_f(a0);
        ov.y = xv.y * sigmoid_f(a1);
        ov.z = xv.z * sigmoid_f(a2);
        ov.w = xv.w * sigmoid_f(a3);
        oq[(size_t)c << 14] = ov;
    }
}

extern "C" void kernel_launch(void* const* d_in, const int* in_sizes, int n_in,
                              void* d_out, int out_size) {
    const float* x  = (const float*)d_in[0];
    const float* w1 = (const float*)d_in[1];
    const float* b1 = (const float*)d_in[2];
    const float* w2 = (const float*)d_in[3];
    const float* b2 = (const float*)d_in[4];
    float* out = (float*)d_out;

    cudaFuncSetAttribute(k_pyr, cudaFuncAttributeMaxDynamicSharedMemorySize, SMEM_PYR);

    k_stats<<<NBC, 256>>>(x);
    k_init<<<dim3(8, 8, NBC), 256>>>(x);
    k_pyr<<<NBC, 256, SMEM_PYR>>>();
    k_field<<<NBC, 256>>>();
    k_mlp<<<(NB*NHW)/1024, 256>>>(x, w1, b1, w2, b2, out);
}

// round 7
// speedup vs baseline: 1.7852x; 1.1515x over previous
#include <cuda_runtime.h>
#include <cuda_fp16.h>
#include <math.h>

#define NB 4
#define NC 128
#define NH 256
#define NW 256
#define NHW (NH*NW)
#define NBC (NB*NC)      // 512 (b,c) planes
#define CM 16
#define PYR_ELEMS 21844  // 128^2+64^2+32^2+16^2+8^2+4^2+2^2

// scratch (device globals: no allocation allowed)
__device__ float   g_thr[2*NBC];
__device__ __half2 g_M0[(size_t)NBC*NHW];        // (pos,neg) packed: max(init, down0)
__device__ __half2 g_r1[(size_t)NBC*128*128];    // resize(down0 -> 128) both signs
__device__ float2  g_pyr[(size_t)NBC*PYR_ELEMS]; // levels 1..7 fp32 (chain precision)
__device__ __half2 g_pyrh[(size_t)NBC*PYR_ELEMS];// same, half2 (consumer copy)
__device__ __half  g_rad[(size_t)NBC*NHW];       // radiance = Lp - Ln

__device__ __constant__ float c_scf[7] = {
    (float)(127.0/255.0), (float)(63.0/255.0), (float)(31.0/255.0),
    (float)(15.0/255.0),  (float)(7.0/255.0),  (float)(3.0/255.0),
    (float)(1.0/255.0)
};
__device__ __constant__ int c_soff[7] = {0, 0, 4096, 5120, 5376, 5440, 5456}; // spyr offsets (k>=1)

__device__ __forceinline__ float sigmoid_f(float t) { return 1.0f / (1.0f + __expf(-t)); }

// ------------------------------------------------------------------ K0: stats
__global__ void __launch_bounds__(256) k_stats(const float* __restrict__ x) {
    int plane = blockIdx.x;
    const float4* p = (const float4*)(x + (size_t)plane * NHW);
    float sp = 0.f, s2p = 0.f, sn = 0.f, s2n = 0.f;
    for (int i = threadIdx.x; i < NHW/4; i += 256) {
        float4 v = __ldg(p + i);
        float a;
        a = fmaxf(v.x,0.f); sp += a; s2p = fmaf(a,a,s2p); a = fmaxf(-v.x,0.f); sn += a; s2n = fmaf(a,a,s2n);
        a = fmaxf(v.y,0.f); sp += a; s2p = fmaf(a,a,s2p); a = fmaxf(-v.y,0.f); sn += a; s2n = fmaf(a,a,s2n);
        a = fmaxf(v.z,0.f); sp += a; s2p = fmaf(a,a,s2p); a = fmaxf(-v.z,0.f); sn += a; s2n = fmaf(a,a,s2n);
        a = fmaxf(v.w,0.f); sp += a; s2p = fmaf(a,a,s2p); a = fmaxf(-v.w,0.f); sn += a; s2n = fmaf(a,a,s2n);
    }
    __shared__ float red[8][4];
    #pragma unroll
    for (int o = 16; o; o >>= 1) {
        sp  += __shfl_down_sync(0xffffffffu, sp,  o);
        s2p += __shfl_down_sync(0xffffffffu, s2p, o);
        sn  += __shfl_down_sync(0xffffffffu, sn,  o);
        s2n += __shfl_down_sync(0xffffffffu, s2n, o);
    }
    int lane = threadIdx.x & 31, w = threadIdx.x >> 5;
    if (lane == 0) { red[w][0] = sp; red[w][1] = s2p; red[w][2] = sn; red[w][3] = s2n; }
    __syncthreads();
    if (threadIdx.x == 0) {
        float SP=0,S2P=0,SN=0,S2N=0;
        for (int i = 0; i < 8; i++) { SP+=red[i][0]; S2P+=red[i][1]; SN+=red[i][2]; S2N+=red[i][3]; }
        const float N = (float)NHW;
        float vp = fmaxf((S2P - SP*SP/N) / (N - 1.f), 0.f);
        g_thr[plane]       = SP/N + 2.f * sqrtf(vp);
        float vn = fmaxf((S2N - SN*SN/N) / (N - 1.f), 0.f);
        g_thr[NBC + plane] = SN/N + 2.f * sqrtf(vn);
    }
}

// -------------------------------------------------- K1: init + M0 + r1 samples
__global__ void __launch_bounds__(256) k_init(const float* __restrict__ x) {
    __shared__ float ip[35][36], inn[35][36];   // init with halo rows ty0-1 .. ty0+33
    __shared__ float dp[33][36], dn[33][36];    // down0 rows ty0 .. ty0+32
    const int bc  = blockIdx.z;
    const int tx0 = blockIdx.x * 32, ty0 = blockIdx.y * 32;
    const float thp = g_thr[bc], thn = g_thr[NBC + bc];
    const float* xp = x + (size_t)bc * NHW;
    const int tid = threadIdx.x;

    for (int idx = tid; idx < 35*35; idx += 256) {
        int r = idx / 35, c = idx % 35;
        int gy = ty0 - 1 + r; gy = min(max(gy, 0), NH-1);
        int gx = tx0 - 1 + c; gx = min(max(gx, 0), NW-1);
        float v  = __ldg(xp + gy*NW + gx);
        float vp = fmaxf(v, 0.f);
        float vn = fmaxf(-v, 0.f);
        ip[r][c]  = vp * (sigmoid_f(100.f*(vp - thp)) + 1e-6f);
        inn[r][c] = vn * (sigmoid_f(100.f*(vn - thn)) + 1e-6f);
    }
    __syncthreads();
    for (int idx = tid; idx < 33*33; idx += 256) {
        int r = idx / 33, c = idx % 33;
        float mp = 0.f, mn = 0.f;
        #pragma unroll
        for (int dr = 0; dr < 3; dr++)
        #pragma unroll
        for (int dc = 0; dc < 3; dc++) {
            mp = fmaxf(mp, ip[r+dr][c+dc]);
            mn = fmaxf(mn, inn[r+dr][c+dc]);
        }
        dp[r][c] = 0.99f * mp;
        dn[r][c] = 0.99f * mn;
    }
    __syncthreads();
    for (int idx = tid; idx < 32*32; idx += 256) {
        int r = idx >> 5, c = idx & 31;
        float m0p = fmaxf(ip[r+1][c+1], dp[r][c]);
        float m0n = fmaxf(inn[r+1][c+1], dn[r][c]);
        g_M0[(size_t)bc*NHW + (size_t)(ty0+r)*NW + (tx0+c)] = __floats2half2_rn(m0p, m0n);
    }
    // r1 = resize(down0 -> 128, align_corners). Tile owns (i,j) iff floor(i*A1)
    // in [ty0,ty0+31] and floor(j*A1) in [tx0,tx0+31] (same fp expr as below).
    const float A1 = 255.0f / 127.0f;
    int i_lo = max(0, (int)((float)ty0 / A1) - 1);
    while (i_lo < 128 && (int)((float)i_lo * A1) < ty0) i_lo++;
    int i_hi = min(127, (int)((float)(ty0+32) / A1) + 1);
    while (i_hi >= i_lo && (int)((float)i_hi * A1) > ty0+31) i_hi--;
    int j_lo = max(0, (int)((float)tx0 / A1) - 1);
    while (j_lo < 128 && (int)((float)j_lo * A1) < tx0) j_lo++;
    int j_hi = min(127, (int)((float)(tx0+32) / A1) + 1);
    while (j_hi >= j_lo && (int)((float)j_hi * A1) > tx0+31) j_hi--;
    int ni = i_hi - i_lo + 1; if (ni < 0) ni = 0;
    int nj = j_hi - j_lo + 1; if (nj < 0) nj = 0;
    for (int idx = tid; idx < ni*nj; idx += 256) {
        int i = i_lo + idx / nj;
        int j = j_lo + idx % nj;
        float fy = (float)i * A1; int i0 = (int)fy; float wy = fy - (float)i0;
        int i1 = min(i0 + 1, NH-1);
        float fx = (float)j * A1; int j0 = (int)fx; float wx = fx - (float)j0;
        int j1 = min(j0 + 1, NW-1);
        int li0 = i0 - ty0, li1 = i1 - ty0, lj0 = j0 - tx0, lj1 = j1 - tx0;
        float vp = (1.f-wy)*((1.f-wx)*dp[li0][lj0] + wx*dp[li0][lj1])
                 +      wy *((1.f-wx)*dp[li1][lj0] + wx*dp[li1][lj1]);
        float vn = (1.f-wy)*((1.f-wx)*dn[li0][lj0] + wx*dn[li0][lj1])
                 +      wy *((1.f-wx)*dn[li1][lj0] + wx*dn[li1][lj1]);
        g_r1[(size_t)bc*16384 + i*128 + j] = __floats2half2_rn(vp, vn);
    }
}

// ----------------------------------------------- K2: pyramid levels 1..7 (fp32 chain)
#define SMEM_PYR (16384*4 + 4096*8)   // S: 16384 half2, R: 4096 float2
__global__ void __launch_bounds__(256) k_pyr() {
    extern __shared__ unsigned char smraw[];
    __half2* S = (__half2*)smraw;                 // r1 staging
    float2*  R = (float2*)(smraw + 16384*4);      // resize buffer (<= 64x64)
    const int bc = blockIdx.x, tid = threadIdx.x;
    const __half2* r1p = g_r1 + (size_t)bc * 16384;
    float2*  pyr  = g_pyr  + (size_t)bc * PYR_ELEMS;
    __half2* pyrh = g_pyrh + (size_t)bc * PYR_ELEMS;

    for (int i = tid; i < 16384; i += 256) S[i] = __ldg(r1p + i);
    __syncthreads();
    // level 1 (size 128): down1 = gamma^2 * maxpool3(r1)
    for (int idx = tid; idx < 16384; idx += 256) {
        int i = idx >> 7, j = idx & 127;
        float mp = 0.f, mn = 0.f;
        #pragma unroll
        for (int dr = -1; dr <= 1; dr++) {
            int ii = min(max(i+dr,0),127) << 7;
            #pragma unroll
            for (int dc = -1; dc <= 1; dc++) {
                int jj = min(max(j+dc,0),127);
                float2 v = __half22float2(S[ii + jj]);
                mp = fmaxf(mp, v.x); mn = fmaxf(mn, v.y);
            }
        }
        float op = 0.9801f*mp, on = 0.9801f*mn;
        pyr[idx]  = make_float2(op, on);
        pyrh[idx] = __floats2half2_rn(op, on);
    }
    __syncthreads();   // block-visible gmem writes
    int off_in = 0, off_out = 16384, sin = 128;
    double gd = 0.9801;
    for (int k = 2; k <= 7; k++) {
        int sout = sin >> 1;
        float ak = (float)((double)(sin-1) / (double)(sout-1));
        const float2* Lv = pyr + off_in;
        for (int idx = tid; idx < sout*sout; idx += 256) {
            int i = idx / sout, j = idx % sout;
            float fy = (float)i * ak; int i0 = (int)fy; float wy = fy - (float)i0; int i1 = min(i0+1, sin-1);
            float fx = (float)j * ak; int j0 = (int)fx; float wx = fx - (float)j0; int j1 = min(j0+1, sin-1);
            float2 a = Lv[i0*sin+j0], b = Lv[i0*sin+j1], c = Lv[i1*sin+j0], d = Lv[i1*sin+j1];
            R[idx] = make_float2(
                (1.f-wy)*((1.f-wx)*a.x + wx*b.x) + wy*((1.f-wx)*c.x + wx*d.x),
                (1.f-wy)*((1.f-wx)*a.y + wx*b.y) + wy*((1.f-wx)*c.y + wx*d.y));
        }
        __syncthreads();
        gd *= gd;                         // gamma^(2^k)
        float gk = (float)gd;
        for (int idx = tid; idx < sout*sout; idx += 256) {
            int i = idx / sout, j = idx % sout;
            float mp = 0.f, mn = 0.f;
            #pragma unroll
            for (int dr = -1; dr <= 1; dr++) {
                int ii = min(max(i+dr,0),sout-1) * sout;
                #pragma unroll
                for (int dc = -1; dc <= 1; dc++) {
                    int jj = min(max(j+dc,0),sout-1);
                    float2 v = R[ii + jj];
                    mp = fmaxf(mp, v.x); mn = fmaxf(mn, v.y);
                }
            }
            float op = gk*mp, on = gk*mn;
            pyr[off_out + idx]  = make_float2(op, on);
            pyrh[off_out + idx] = __floats2half2_rn(op, on);
        }
        __syncthreads();
        off_in = off_out; off_out += sout*sout; sin = sout;
    }
}

// --------- K3: radiance. 8 rows/iter, double-buffered half2 rowbuf, half2 consume
__global__ void __launch_bounds__(256, 4) k_field() {
    __shared__ __half2 spyr[5460];       // levels 2..7 (64^2..2^2)
    __shared__ __half2 rb[2][8][256];    // y-lerped rows of all 7 levels (half2)
    const int bc  = blockIdx.x;
    const int tid = threadIdx.x;
    const __half2* pyrh = g_pyrh + (size_t)bc * PYR_ELEMS;
    for (int i = tid; i < 5460; i += 256) spyr[i] = __ldg(&pyrh[16384 + i]);

    // consume constants: absolute rb column offsets + half2 weights per level
    const int rboff[7] = {0, 128, 192, 224, 240, 248, 252};
    int j0a[7], j1a[7]; __half2 w2a[7], om2a[7];
    #pragma unroll
    for (int k = 0; k < 7; k++) {
        int s = 128 >> k;
        float fx = (float)tid * c_scf[k];
        int j0 = (int)fx; float wx = fx - (float)j0; int j1 = min(j0+1, s-1);
        j0a[k] = rboff[k] + j0; j1a[k] = rboff[k] + j1;
        w2a[k]  = __floats2half2_rn(wx, wx);
        om2a[k] = __floats2half2_rn(1.f-wx, 1.f-wx);
    }

    // build constants: thread tid builds rowbuf position tid = (level kb, index jb)
    int kb, jb;
    if      (tid < 128) { kb = 0; jb = tid;       }
    else if (tid < 192) { kb = 1; jb = tid - 128; }
    else if (tid < 224) { kb = 2; jb = tid - 192; }
    else if (tid < 240) { kb = 3; jb = tid - 224; }
    else if (tid < 248) { kb = 4; jb = tid - 240; }
    else if (tid < 252) { kb = 5; jb = tid - 248; }
    else                { kb = 6; jb = tid - 252; }
    const bool doB = (tid < 254);
    const int   sb  = 128 >> kb;
    const float scb = c_scf[kb];
    const int   sob = c_soff[kb];
    __syncthreads();   // spyr visible

    // build one y-lerped value (rounded to half2) for output row y at (kb, jb)
    auto buildv = [&](int y) -> __half2 {
        float fy = (float)y * scb;
        int i0 = (int)fy; float wy = fy - (float)i0; int i1 = min(i0+1, sb-1);
        float2 a, b;
        if (kb == 0) {
            a = __half22float2(__ldg(&pyrh[i0*128 + jb]));
            b = __half22float2(__ldg(&pyrh[i1*128 + jb]));
        } else {
            a = __half22float2(spyr[sob + i0*sb + jb]);
            b = __half22float2(spyr[sob + i1*sb + jb]);
        }
        return __floats2half2_rn((1.f-wy)*a.x + wy*b.x, (1.f-wy)*a.y + wy*b.y);
    };

    // prologue: rows 0..7 into buffer 0
    if (doB) {
        #pragma unroll
        for (int r = 0; r < 8; r++) rb[0][r][tid] = buildv(r);
    }
    __syncthreads();

    const __half2* M0p = g_M0 + (size_t)bc * NHW + tid;
    __half* radp = g_rad + (size_t)bc * NHW + tid;

    int buf = 0;
    for (int y0 = 0; y0 < NH; y0 += 8) {
        // prefetch next block's build values (loads overlap consume below)
        __half2 nb[8];
        const bool more = (y0 + 8 < NH);
        if (more && doB) {
            #pragma unroll
            for (int r = 0; r < 8; r++) nb[r] = buildv(y0 + 8 + r);
        }
        // consume 8 rows at column tid, packed half2 (pos,neg) math
        #pragma unroll
        for (int r = 0; r < 8; r++) {
            const __half2* rowp = &rb[buf][r][0];
            __half2 U = __ldg(M0p + (y0+r)*NW);   // start from M0 (>= 0 fields)
            #pragma unroll
            for (int k = 0; k < 7; k++) {
                __half2 a = rowp[j0a[k]];
                __half2 b = rowp[j1a[k]];
                U = __hmax2(U, __hfma2(w2a[k], b, __hmul2(om2a[k], a)));
            }
            float2 uf = __half22float2(U);
            radp[(y0+r)*NW] = __float2half_rn(uf.x - uf.y);
        }
        if (more && doB) {
            #pragma unroll
            for (int r = 0; r < 8; r++) rb[buf^1][r][tid] = nb[r];
        }
        __syncthreads();
        buf ^= 1;
    }
}

// --------------------------- K4: 1x1-conv MLP + modulate (2 px/thread, 512 CTAs)
__global__ void __launch_bounds__(256) k_mlp(
    const float* __restrict__ x,
    const float* __restrict__ w1, const float* __restrict__ b1,
    const float* __restrict__ w2, const float* __restrict__ b2,
    float* __restrict__ out)
{
    __shared__ float sw1[CM*NC], sw2[NC*CM], sb1[CM], sb2[NC];
    const int tid = threadIdx.x;
    for (int i = tid; i < CM*NC; i += 256) { sw1[i] = w1[i]; sw2[i] = w2[i]; }
    if (tid < CM) sb1[tid] = b1[tid];
    if (tid < NC) sb2[tid] = b2[tid];
    __syncthreads();

    int g  = blockIdx.x * 256 + tid;      // pixel-pair index (131072 total)
    int b  = g >> 15;                     // 32768 pairs per batch
    int hw = (g & 32767) << 1;
    size_t base = ((size_t)(b*NC) << 16) + hw;
    const __half2* rp = (const __half2*)(g_rad + base);
    const float2*  xp = (const float2*) (x     + base);
    float2*        op = (float2*)       (out   + base);

    float h0[CM], h1[CM];
    #pragma unroll
    for (int o = 0; o < CM; o++) { h0[o] = sb1[o]; h1[o] = sb1[o]; }
    for (int c = 0; c < NC; c++) {
        float2 r = __half22float2(__ldg(rp + ((size_t)c << 15)));
        #pragma unroll
        for (int o = 0; o < CM; o++) {
            float w = sw1[o*NC + c];
            h0[o] = fmaf(w, r.x, h0[o]);
            h1[o] = fmaf(w, r.y, h1[o]);
        }
    }
    #pragma unroll
    for (int o = 0; o < CM; o++) { h0[o] = fmaxf(h0[o], 0.f); h1[o] = fmaxf(h1[o], 0.f); }
    for (int c = 0; c < NC; c++) {
        float a0 = sb2[c], a1 = sb2[c];
        #pragma unroll
        for (int o = 0; o < CM; o++) {
            float w = sw2[c*CM + o];
            a0 = fmaf(w, h0[o], a0);
            a1 = fmaf(w, h1[o], a1);
        }
        float2 xv = __ldg(xp + ((size_t)c << 15));
        float2 ov;
        ov.x = xv.x * sigmoid_f(a0);
        ov.y = xv.y * sigmoid_f(a1);
        op[(size_t)c << 15] = ov;
    }
}

extern "C" void kernel_launch(void* const* d_in, const int* in_sizes, int n_in,
                              void* d_out, int out_size) {
    const float* x  = (const float*)d_in[0];
    const float* w1 = (const float*)d_in[1];
    const float* b1 = (const float*)d_in[2];
    const float* w2 = (const float*)d_in[3];
    const float* b2 = (const float*)d_in[4];
    float* out = (float*)d_out;

    cudaFuncSetAttribute(k_pyr, cudaFuncAttributeMaxDynamicSharedMemorySize, SMEM_PYR);

    k_stats<<<NBC, 256>>>(x);
    k_init<<<dim3(8, 8, NBC), 256>>>(x);
    k_pyr<<<NBC, 256, SMEM_PYR>>>();
    k_field<<<NBC, 256>>>();
    k_mlp<<<(NB*NHW)/512, 256>>>(x, w1, b1, w2, b2, out);
}